// round 4
// baseline (speedup 1.0000x reference)
#include <cuda_runtime.h>

#define BATCH 16
#define LEN   512
#define IDIM  300
#define HDIM  32
#define ODIM  15
#define GDIM  96
#define TI    64
#define KSTR  36          // smem row stride (floats), 16B-aligned, conflict-free

typedef unsigned long long ull;

// Scratch as float4 arrays (guarantees 16B alignment for vector access)
__device__ float4 g_gx4 [BATCH * LEN * GDIM / 4];
__device__ float4 g_out4[BATCH * LEN * HDIM / 4];
__device__ float4 g_qh4 [BATCH * LEN * HDIM / 4];
__device__ float4 g_kh4 [BATCH * LEN * HDIM / 4];
#define g_gx  ((float*)g_gx4)
#define g_out ((float*)g_out4)
#define g_qh  ((float*)g_qh4)
#define g_kh  ((float*)g_kh4)

__device__ __forceinline__ float tanh_fast(float x) {
    float y;
    asm("tanh.approx.f32 %0, %1;" : "=f"(y) : "f"(x));
    return y;
}

// ---------------------------------------------------------------------------
// K1: gx = x @ w_ih^T + b_ih   (M=8192, N=96, K=300)
// ---------------------------------------------------------------------------
__global__ __launch_bounds__(256) void gx_kernel(
    const float* __restrict__ x,
    const float* __restrict__ w_ih,
    const float* __restrict__ b_ih)
{
    __shared__ float xs[16][65];
    __shared__ float ws[16][97];

    const int m0 = blockIdx.x * 64;
    const int tx = threadIdx.x & 15;
    const int ty = threadIdx.x >> 4;

    float acc[4][6];
#pragma unroll
    for (int i = 0; i < 4; i++)
#pragma unroll
        for (int j = 0; j < 6; j++) acc[i][j] = 0.f;

    for (int kt = 0; kt < IDIM; kt += 16) {
        for (int idx = threadIdx.x; idx < 64 * 16; idx += 256) {
            int r = idx >> 4, kk = idx & 15;
            int k = kt + kk;
            xs[kk][r] = (k < IDIM) ? x[(m0 + r) * IDIM + k] : 0.f;
        }
        for (int idx = threadIdx.x; idx < 96 * 16; idx += 256) {
            int c = idx >> 4, kk = idx & 15;
            int k = kt + kk;
            ws[kk][c] = (k < IDIM) ? w_ih[c * IDIM + k] : 0.f;
        }
        __syncthreads();
#pragma unroll
        for (int kk = 0; kk < 16; kk++) {
            float xv[4], wv[6];
#pragma unroll
            for (int i = 0; i < 4; i++) xv[i] = xs[kk][ty * 4 + i];
#pragma unroll
            for (int j = 0; j < 6; j++) wv[j] = ws[kk][tx * 6 + j];
#pragma unroll
            for (int i = 0; i < 4; i++)
#pragma unroll
                for (int j = 0; j < 6; j++)
                    acc[i][j] = fmaf(xv[i], wv[j], acc[i][j]);
        }
        __syncthreads();
    }
#pragma unroll
    for (int i = 0; i < 4; i++) {
        int m = m0 + ty * 4 + i;
#pragma unroll
        for (int j = 0; j < 6; j++) {
            int c = tx * 6 + j;
            g_gx[m * GDIM + c] = acc[i][j] + b_ih[c];
        }
    }
}

// ---------------------------------------------------------------------------
// K2: GRU recurrence. 3 warps per batch (one per gate), replicated hidden
// state across warps, shfl-broadcast dot, ONE barrier per step.
// ---------------------------------------------------------------------------
__global__ __launch_bounds__(96) void gru_kernel(
    const float* __restrict__ w_hh,
    const float* __restrict__ b_hh,
    const float* __restrict__ h0,
    const int*   __restrict__ x_lens)
{
    __shared__ float rsh[2][32], zsh[2][32], nhsh[2][32], nxsh[2][32];

    const int b   = blockIdx.x;
    const int tid = threadIdx.x;
    const int g   = tid >> 5;     // gate: 0=r, 1=z, 2=n
    const int h   = tid & 31;

    float w[HDIM];
#pragma unroll
    for (int k = 0; k < HDIM; k++)
        w[k] = w_hh[(g * HDIM + h) * HDIM + k];
    const float bias = b_hh[g * HDIM + h];

    float hcur = h0[b * HDIM + h];           // replicated in all 3 warps
    const int len = x_lens[b];
    const float* gxb = g_gx + (size_t)b * LEN * GDIM + tid;
    float* outb = g_out + (size_t)b * LEN * HDIM;

    float gxp[2];
    gxp[0] = gxb[0];
    gxp[1] = gxb[GDIM];

    for (int t = 0; t < LEN; t++) {
        const int s = t & 1;
        const float gxv = gxp[s];
        if (t + 2 < LEN) gxp[s] = gxb[(t + 2) * GDIM];

        // gate dot: w row . h  via shfl broadcast, 4 independent chains
        float a0 = bias, a1 = 0.f, a2 = 0.f, a3 = 0.f;
#pragma unroll
        for (int k = 0; k < HDIM; k += 4) {
            a0 = fmaf(w[k],     __shfl_sync(0xffffffffu, hcur, k),     a0);
            a1 = fmaf(w[k + 1], __shfl_sync(0xffffffffu, hcur, k + 1), a1);
            a2 = fmaf(w[k + 2], __shfl_sync(0xffffffffu, hcur, k + 2), a2);
            a3 = fmaf(w[k + 3], __shfl_sync(0xffffffffu, hcur, k + 3), a3);
        }
        const float dot = (a0 + a1) + (a2 + a3);

        if (g == 2) {
            nhsh[s][h] = dot;
            nxsh[s][h] = gxv;
        } else {
            const float sg = fmaf(tanh_fast((gxv + dot) * 0.5f), 0.5f, 0.5f);
            if (g == 0) rsh[s][h] = sg; else zsh[s][h] = sg;
        }
        __syncthreads();

        // all warps redundantly update hcur (keeps replication, no 2nd barrier)
        const float r  = rsh[s][h],  z  = zsh[s][h];
        const float nh = nhsh[s][h], nx = nxsh[s][h];
        const float n  = tanh_fast(fmaf(r, nh, nx));
        hcur = fmaf(z, hcur - n, n);
        if (g == 2) outb[t * HDIM + h] = (t < len) ? hcur : 0.f;
    }
}

// ---------------------------------------------------------------------------
// K3: qh = out@fch_w^T, kh = out@fco_w^T
// ---------------------------------------------------------------------------
__global__ __launch_bounds__(256) void qk_kernel(
    const float* __restrict__ fch_w,
    const float* __restrict__ fco_w)
{
    __shared__ float wq[HDIM][HDIM + 1];
    __shared__ float wk[HDIM][HDIM + 1];
    __shared__ float os[8][HDIM];

    const int tid = threadIdx.x;
    for (int idx = tid; idx < HDIM * HDIM; idx += 256) {
        int c = idx >> 5, k = idx & 31;
        wq[k][c] = fch_w[c * HDIM + k];
        wk[k][c] = fco_w[c * HDIM + k];
    }
    const int m0 = blockIdx.x * 8;
    const int r = tid >> 5, c = tid & 31;
    os[r][c] = g_out[(m0 + r) * HDIM + c];
    __syncthreads();

    float aq = 0.f, ak = 0.f;
#pragma unroll
    for (int k = 0; k < HDIM; k++) {
        float o = os[r][k];
        aq = fmaf(o, wq[k][c], aq);
        ak = fmaf(o, wk[k][c], ak);
    }
    g_qh[(m0 + r) * HDIM + c] = aq;
    g_kh[(m0 + r) * HDIM + c] = ak;
}

// ---------------------------------------------------------------------------
// K4: fused attention, single pass per chunk (phase A+B fused via shfl),
// fixed-shift softmax (no max pass).
// ---------------------------------------------------------------------------
__global__ __launch_bounds__(512) void attn_kernel(
    const float* __restrict__ v,
    const float* __restrict__ fc_w,
    const float* __restrict__ fc_b,
    const int*   __restrict__ x_lens,
    float* __restrict__ y)
{
    extern __shared__ float sm[];
    float* ks   = sm;                     // [512][36]
    float* os   = ks  + LEN * KSTR;       // [512][36]
    float* vsh  = os  + LEN * KSTR;       // 32
    float* osum = vsh + 32;               // 32
    float* ctxs = osum + 32;              // [16][33]
    float* fcw  = ctxs + 16 * 33;         // [15][33]
    float* fcb  = fcw + ODIM * 33;        // 16

    const int b   = blockIdx.y;
    const int i0  = blockIdx.x * TI;
    const int tid = threadIdx.x;
    const int wid = tid >> 5, lane = tid & 31;

    for (int idx = tid; idx < LEN * 8; idx += 512) {
        int j = idx >> 3, q = idx & 7;
        float4 kv = g_kh4[(b * LEN + j) * 8 + q];
        float4 ov = g_out4[(b * LEN + j) * 8 + q];
        *(float4*)(ks + j * KSTR + q * 4) = kv;
        *(float4*)(os + j * KSTR + q * 4) = ov;
    }
    if (tid < HDIM) vsh[tid] = v[tid];
    if (tid < ODIM * HDIM) {
        int o = tid / HDIM, h = tid % HDIM;
        fcw[o * 33 + h] = fc_w[tid];
    }
    if (tid < ODIM) fcb[tid] = fc_b[tid];
    __syncthreads();

    // osum[h] = sum_j out[j][h]
    {
        float p = 0.f;
#pragma unroll
        for (int jj = 0; jj < 32; jj++)
            p += os[(wid * 32 + jj) * KSTR + lane];
        ctxs[wid * 33 + lane] = p;
    }
    __syncthreads();
    if (tid < HDIM) {
        float t = 0.f;
#pragma unroll
        for (int w = 0; w < 16; w++) t += ctxs[w * 33 + tid];
        osum[tid] = t;
    }
    __syncthreads();

    const int len  = x_lens[b];
    const int jc   = (len + 31) >> 5;
    const int tail = LEN - jc * 32;

    float vr[HDIM];
#pragma unroll
    for (int h = 0; h < HDIM; h++) vr[h] = vsh[h];
    float S = 0.f;
#pragma unroll
    for (int h = 0; h < HDIM; h++) S += fabsf(vr[h]);

    for (int ii = wid; ii < TI; ii += 16) {
        const int i = i0 + ii;
        const float* qrow = g_qh + (size_t)(b * LEN + i) * HDIM;

        union { float4 v4[8]; float f[HDIM]; } qu;
#pragma unroll
        for (int q = 0; q < 8; q++)
            qu.v4[q] = g_qh4[(b * LEN + i) * 8 + q];

        // e_pad = sum_h v_h * tanh(q_h)
        float ep = vsh[lane] * tanh_fast(__ldg(qrow + lane));
#pragma unroll
        for (int s = 16; s > 0; s >>= 1)
            ep += __shfl_xor_sync(0xffffffffu, ep, s);

        float ssum = 0.f, ctx = 0.f;
        for (int c = 0; c < jc; c++) {
            const float* krow = ks + (c * 32 + lane) * KSTR;
            union { float4 v4[8]; float f[HDIM]; } ku;
#pragma unroll
            for (int q = 0; q < 8; q++)
                ku.v4[q] = *(const float4*)(krow + q * 4);

            float e = 0.f;
#pragma unroll
            for (int h = 0; h < HDIM; h++)
                e = fmaf(vr[h], tanh_fast(qu.f[h] + ku.f[h]), e);

            ssum += __expf(e - S);

            const float* orow = os + (c * 32) * KSTR + lane;
#pragma unroll
            for (int jj = 0; jj < 32; jj++) {
                float ej = __shfl_sync(0xffffffffu, e, jj);
                ctx = fmaf(ej, orow[jj * KSTR], ctx);
            }
        }
#pragma unroll
        for (int s = 16; s > 0; s >>= 1)
            ssum += __shfl_xor_sync(0xffffffffu, ssum, s);
        if (tail > 0) ssum += (float)tail * __expf(ep - S);
        const float lse = S + __logf(ssum);

        ctx = fmaf(-lse, osum[lane], ctx);

        ctxs[wid * 33 + lane] = ctx;
        __syncwarp();
        if (lane < ODIM) {
            float r = fcb[lane];
#pragma unroll
            for (int h = 0; h < HDIM; h++)
                r = fmaf(fcw[lane * 33 + h], ctxs[wid * 33 + h], r);
            y[(size_t)(b * LEN + i) * ODIM + lane] = r;
        }
        __syncwarp();
    }
}

// ---------------------------------------------------------------------------
extern "C" void kernel_launch(void* const* d_in, const int* in_sizes, int n_in,
                              void* d_out, int out_size)
{
    const float* x      = (const float*)d_in[0];
    const int*   x_lens = (const int*)  d_in[1];
    const float* h0     = (const float*)d_in[2];
    const float* w_ih   = (const float*)d_in[3];
    const float* w_hh   = (const float*)d_in[4];
    const float* b_ih   = (const float*)d_in[5];
    const float* b_hh   = (const float*)d_in[6];
    const float* fc_w   = (const float*)d_in[7];
    const float* fc_b   = (const float*)d_in[8];
    const float* fch_w  = (const float*)d_in[9];
    const float* fco_w  = (const float*)d_in[10];
    const float* v      = (const float*)d_in[11];
    float* y = (float*)d_out;

    const size_t attn_smem = (size_t)(2 * LEN * KSTR + 32 + 32 + 16 * 33 +
                                      ODIM * 33 + 16) * sizeof(float);
    cudaFuncSetAttribute(attn_kernel,
                         cudaFuncAttributeMaxDynamicSharedMemorySize,
                         (int)attn_smem);

    gx_kernel <<<(BATCH * LEN) / 64, 256>>>(x, w_ih, b_ih);
    gru_kernel<<<BATCH, 96>>>(w_hh, b_hh, h0, x_lens);
    qk_kernel <<<(BATCH * LEN) / 8, 256>>>(fch_w, fco_w);
    attn_kernel<<<dim3(LEN / TI, BATCH), 512, attn_smem>>>(v, fc_w, fc_b,
                                                           x_lens, y);
}

// round 5
// speedup vs baseline: 1.4844x; 1.4844x over previous
#include <cuda_runtime.h>

#define BATCH 16
#define LEN   512
#define IDIM  300
#define HDIM  32
#define ODIM  15
#define GDIM  96
#define TI    64
#define KSTR  36          // smem row stride (floats), 16B-aligned, conflict-free

typedef unsigned long long ull;

// Scratch as float4 arrays (guarantees 16B alignment for vector access)
__device__ float4 g_gx4 [BATCH * LEN * GDIM / 4];
__device__ float4 g_out4[BATCH * LEN * HDIM / 4];
__device__ float4 g_qh4 [BATCH * LEN * HDIM / 4];
__device__ float4 g_kh4 [BATCH * LEN * HDIM / 4];
#define g_gx  ((float*)g_gx4)
#define g_out ((float*)g_out4)
#define g_qh  ((float*)g_qh4)
#define g_kh  ((float*)g_kh4)

__device__ __forceinline__ float tanh_fast(float x) {
    float y;
    asm("tanh.approx.f32 %0, %1;" : "=f"(y) : "f"(x));
    return y;
}
__device__ __forceinline__ ull ffma2u(ull a, ull b, ull c) {
    ull d;
    asm("fma.rn.f32x2 %0, %1, %2, %3;" : "=l"(d) : "l"(a), "l"(b), "l"(c));
    return d;
}
__device__ __forceinline__ ull add2u(ull a, ull b) {
    ull d;
    asm("add.rn.f32x2 %0, %1, %2;" : "=l"(d) : "l"(a), "l"(b));
    return d;
}
__device__ __forceinline__ ull pack2(float lo, float hi) {
    ull d;
    asm("mov.b64 %0, {%1, %2};" : "=l"(d) : "f"(lo), "f"(hi));
    return d;
}
__device__ __forceinline__ float hsum2(ull a) {
    float lo, hi;
    asm("mov.b64 {%0, %1}, %2;" : "=f"(lo), "=f"(hi) : "l"(a));
    return lo + hi;
}

// ---------------------------------------------------------------------------
// K1: gx = x @ w_ih^T + b_ih   (M=8192, N=96, K=300)
// ---------------------------------------------------------------------------
__global__ __launch_bounds__(256) void gx_kernel(
    const float* __restrict__ x,
    const float* __restrict__ w_ih,
    const float* __restrict__ b_ih)
{
    __shared__ float xs[16][65];
    __shared__ float ws[16][97];

    const int m0 = blockIdx.x * 64;
    const int tx = threadIdx.x & 15;
    const int ty = threadIdx.x >> 4;

    float acc[4][6];
#pragma unroll
    for (int i = 0; i < 4; i++)
#pragma unroll
        for (int j = 0; j < 6; j++) acc[i][j] = 0.f;

    for (int kt = 0; kt < IDIM; kt += 16) {
        for (int idx = threadIdx.x; idx < 64 * 16; idx += 256) {
            int r = idx >> 4, kk = idx & 15;
            int k = kt + kk;
            xs[kk][r] = (k < IDIM) ? x[(m0 + r) * IDIM + k] : 0.f;
        }
        for (int idx = threadIdx.x; idx < 96 * 16; idx += 256) {
            int c = idx >> 4, kk = idx & 15;
            int k = kt + kk;
            ws[kk][c] = (k < IDIM) ? w_ih[c * IDIM + k] : 0.f;
        }
        __syncthreads();
#pragma unroll
        for (int kk = 0; kk < 16; kk++) {
            float xv[4], wv[6];
#pragma unroll
            for (int i = 0; i < 4; i++) xv[i] = xs[kk][ty * 4 + i];
#pragma unroll
            for (int j = 0; j < 6; j++) wv[j] = ws[kk][tx * 6 + j];
#pragma unroll
            for (int i = 0; i < 4; i++)
#pragma unroll
                for (int j = 0; j < 6; j++)
                    acc[i][j] = fmaf(xv[i], wv[j], acc[i][j]);
        }
        __syncthreads();
    }
#pragma unroll
    for (int i = 0; i < 4; i++) {
        int m = m0 + ty * 4 + i;
#pragma unroll
        for (int j = 0; j < 6; j++) {
            int c = tx * 6 + j;
            g_gx[m * GDIM + c] = acc[i][j] + b_ih[c];
        }
    }
}

// ---------------------------------------------------------------------------
// K2: GRU recurrence. One warp per batch. Pure shfl-pair broadcast (no smem,
// no barriers), FFMA2 split chains, depth-4 gx prefetch.
// ---------------------------------------------------------------------------
__global__ __launch_bounds__(32) void gru_kernel(
    const float* __restrict__ w_hh,
    const float* __restrict__ b_hh,
    const float* __restrict__ h0,
    const int*   __restrict__ x_lens)
{
    const int b = blockIdx.x;
    const int h = threadIdx.x;

    const ull* w8 = (const ull*)w_hh;   // [96][16] packed pairs
    ull wr2[16], wz2[16], wn2[16];
#pragma unroll
    for (int k = 0; k < 16; k++) {
        wr2[k] = w8[(0 * HDIM + h) * 16 + k];
        wz2[k] = w8[(1 * HDIM + h) * 16 + k];
        wn2[k] = w8[(2 * HDIM + h) * 16 + k];
    }
    const ull brp = pack2(b_hh[h], 0.f);
    const ull bzp = pack2(b_hh[HDIM + h], 0.f);
    const ull bnp = pack2(b_hh[2 * HDIM + h], 0.f);

    float hcur = h0[b * HDIM + h];
    const int len = x_lens[b];
    const float* gxb = g_gx + (size_t)b * LEN * GDIM;
    float* outb = g_out + (size_t)b * LEN * HDIM;

    // depth-4 prefetch of gx
    float rxb[4], zxb[4], nxb[4];
#pragma unroll
    for (int t = 0; t < 4; t++) {
        const float* p = gxb + t * GDIM;
        rxb[t] = p[h]; zxb[t] = p[HDIM + h]; nxb[t] = p[2 * HDIM + h];
    }

#pragma unroll 4
    for (int t = 0; t < LEN; t++) {
        const int s = t & 3;
        const float rx = rxb[s], zx = zxb[s], nx = nxb[s];
        if (t + 4 < LEN) {
            const float* p = gxb + (t + 4) * GDIM;
            rxb[s] = p[h]; zxb[s] = p[HDIM + h]; nxb[s] = p[2 * HDIM + h];
        }

        // broadcast h pairs via shfl, FFMA2 with 4 independent chains/gate
        ull ra[4] = {brp, 0ull, 0ull, 0ull};
        ull za[4] = {bzp, 0ull, 0ull, 0ull};
        ull na[4] = {bnp, 0ull, 0ull, 0ull};
#pragma unroll
        for (int k = 0; k < 16; k++) {
            const float lo = __shfl_sync(0xffffffffu, hcur, 2 * k);
            const float hi = __shfl_sync(0xffffffffu, hcur, 2 * k + 1);
            const ull h2 = pack2(lo, hi);
            const int p = k & 3;
            ra[p] = ffma2u(wr2[k], h2, ra[p]);
            za[p] = ffma2u(wz2[k], h2, za[p]);
            na[p] = ffma2u(wn2[k], h2, na[p]);
        }
        const float rh = hsum2(add2u(add2u(ra[0], ra[1]), add2u(ra[2], ra[3])));
        const float zh = hsum2(add2u(add2u(za[0], za[1]), add2u(za[2], za[3])));
        const float nh = hsum2(add2u(add2u(na[0], na[1]), add2u(na[2], na[3])));

        const float r = fmaf(tanh_fast((rx + rh) * 0.5f), 0.5f, 0.5f);
        const float z = fmaf(tanh_fast((zx + zh) * 0.5f), 0.5f, 0.5f);
        const float n = tanh_fast(fmaf(r, nh, nx));
        hcur = fmaf(z, hcur - n, n);
        outb[t * HDIM + h] = (t < len) ? hcur : 0.f;
    }
}

// ---------------------------------------------------------------------------
// K3: qh = out@fch_w^T, kh = out@fco_w^T
// ---------------------------------------------------------------------------
__global__ __launch_bounds__(256) void qk_kernel(
    const float* __restrict__ fch_w,
    const float* __restrict__ fco_w)
{
    __shared__ float wq[HDIM][HDIM + 1];
    __shared__ float wk[HDIM][HDIM + 1];
    __shared__ float os[8][HDIM];

    const int tid = threadIdx.x;
    for (int idx = tid; idx < HDIM * HDIM; idx += 256) {
        int c = idx >> 5, k = idx & 31;
        wq[k][c] = fch_w[c * HDIM + k];
        wk[k][c] = fco_w[c * HDIM + k];
    }
    const int m0 = blockIdx.x * 8;
    const int r = tid >> 5, c = tid & 31;
    os[r][c] = g_out[(m0 + r) * HDIM + c];
    __syncthreads();

    float aq = 0.f, ak = 0.f;
#pragma unroll
    for (int k = 0; k < HDIM; k++) {
        float o = os[r][k];
        aq = fmaf(o, wq[k][c], aq);
        ak = fmaf(o, wk[k][c], ak);
    }
    g_qh[(m0 + r) * HDIM + c] = aq;
    g_kh[(m0 + r) * HDIM + c] = ak;
}

// ---------------------------------------------------------------------------
// K4: fused attention, single pass per chunk (phase A+B fused via shfl),
// fixed-shift softmax (no max pass).
// ---------------------------------------------------------------------------
__global__ __launch_bounds__(512) void attn_kernel(
    const float* __restrict__ v,
    const float* __restrict__ fc_w,
    const float* __restrict__ fc_b,
    const int*   __restrict__ x_lens,
    float* __restrict__ y)
{
    extern __shared__ float sm[];
    float* ks   = sm;                     // [512][36]
    float* os   = ks  + LEN * KSTR;       // [512][36]
    float* vsh  = os  + LEN * KSTR;       // 32
    float* osum = vsh + 32;               // 32
    float* ctxs = osum + 32;              // [16][33]
    float* fcw  = ctxs + 16 * 33;         // [15][33]
    float* fcb  = fcw + ODIM * 33;        // 16

    const int b   = blockIdx.y;
    const int i0  = blockIdx.x * TI;
    const int tid = threadIdx.x;
    const int wid = tid >> 5, lane = tid & 31;

    for (int idx = tid; idx < LEN * 8; idx += 512) {
        int j = idx >> 3, q = idx & 7;
        float4 kv = g_kh4[(b * LEN + j) * 8 + q];
        float4 ov = g_out4[(b * LEN + j) * 8 + q];
        *(float4*)(ks + j * KSTR + q * 4) = kv;
        *(float4*)(os + j * KSTR + q * 4) = ov;
    }
    if (tid < HDIM) vsh[tid] = v[tid];
    if (tid < ODIM * HDIM) {
        int o = tid / HDIM, h = tid % HDIM;
        fcw[o * 33 + h] = fc_w[tid];
    }
    if (tid < ODIM) fcb[tid] = fc_b[tid];
    __syncthreads();

    // osum[h] = sum_j out[j][h]
    {
        float p = 0.f;
#pragma unroll
        for (int jj = 0; jj < 32; jj++)
            p += os[(wid * 32 + jj) * KSTR + lane];
        ctxs[wid * 33 + lane] = p;
    }
    __syncthreads();
    if (tid < HDIM) {
        float t = 0.f;
#pragma unroll
        for (int w = 0; w < 16; w++) t += ctxs[w * 33 + tid];
        osum[tid] = t;
    }
    __syncthreads();

    const int len  = x_lens[b];
    const int jc   = (len + 31) >> 5;
    const int tail = LEN - jc * 32;

    float vr[HDIM];
#pragma unroll
    for (int h = 0; h < HDIM; h++) vr[h] = vsh[h];
    float S = 0.f;
#pragma unroll
    for (int h = 0; h < HDIM; h++) S += fabsf(vr[h]);

    for (int ii = wid; ii < TI; ii += 16) {
        const int i = i0 + ii;
        const float* qrow = g_qh + (size_t)(b * LEN + i) * HDIM;

        union { float4 v4[8]; float f[HDIM]; } qu;
#pragma unroll
        for (int q = 0; q < 8; q++)
            qu.v4[q] = g_qh4[(b * LEN + i) * 8 + q];

        // e_pad = sum_h v_h * tanh(q_h)
        float ep = vsh[lane] * tanh_fast(__ldg(qrow + lane));
#pragma unroll
        for (int s = 16; s > 0; s >>= 1)
            ep += __shfl_xor_sync(0xffffffffu, ep, s);

        float ssum = 0.f, ctx = 0.f;
        for (int c = 0; c < jc; c++) {
            const float* krow = ks + (c * 32 + lane) * KSTR;
            union { float4 v4[8]; float f[HDIM]; } ku;
#pragma unroll
            for (int q = 0; q < 8; q++)
                ku.v4[q] = *(const float4*)(krow + q * 4);

            float e = 0.f;
#pragma unroll
            for (int h = 0; h < HDIM; h++)
                e = fmaf(vr[h], tanh_fast(qu.f[h] + ku.f[h]), e);

            ssum += __expf(e - S);

            const float* orow = os + (c * 32) * KSTR + lane;
#pragma unroll
            for (int jj = 0; jj < 32; jj++) {
                float ej = __shfl_sync(0xffffffffu, e, jj);
                ctx = fmaf(ej, orow[jj * KSTR], ctx);
            }
        }
#pragma unroll
        for (int s = 16; s > 0; s >>= 1)
            ssum += __shfl_xor_sync(0xffffffffu, ssum, s);
        if (tail > 0) ssum += (float)tail * __expf(ep - S);
        const float lse = S + __logf(ssum);

        ctx = fmaf(-lse, osum[lane], ctx);

        ctxs[wid * 33 + lane] = ctx;
        __syncwarp();
        if (lane < ODIM) {
            float r = fcb[lane];
#pragma unroll
            for (int h = 0; h < HDIM; h++)
                r = fmaf(fcw[lane * 33 + h], ctxs[wid * 33 + h], r);
            y[(size_t)(b * LEN + i) * ODIM + lane] = r;
        }
        __syncwarp();
    }
}

// ---------------------------------------------------------------------------
extern "C" void kernel_launch(void* const* d_in, const int* in_sizes, int n_in,
                              void* d_out, int out_size)
{
    const float* x      = (const float*)d_in[0];
    const int*   x_lens = (const int*)  d_in[1];
    const float* h0     = (const float*)d_in[2];
    const float* w_ih   = (const float*)d_in[3];
    const float* w_hh   = (const float*)d_in[4];
    const float* b_ih   = (const float*)d_in[5];
    const float* b_hh   = (const float*)d_in[6];
    const float* fc_w   = (const float*)d_in[7];
    const float* fc_b   = (const float*)d_in[8];
    const float* fch_w  = (const float*)d_in[9];
    const float* fco_w  = (const float*)d_in[10];
    const float* v      = (const float*)d_in[11];
    float* y = (float*)d_out;

    const size_t attn_smem = (size_t)(2 * LEN * KSTR + 32 + 32 + 16 * 33 +
                                      ODIM * 33 + 16) * sizeof(float);
    cudaFuncSetAttribute(attn_kernel,
                         cudaFuncAttributeMaxDynamicSharedMemorySize,
                         (int)attn_smem);

    gx_kernel <<<(BATCH * LEN) / 64, 256>>>(x, w_ih, b_ih);
    gru_kernel<<<BATCH, 32>>>(w_hh, b_hh, h0, x_lens);
    qk_kernel <<<(BATCH * LEN) / 8, 256>>>(fch_w, fco_w);
    attn_kernel<<<dim3(LEN / TI, BATCH), 512, attn_smem>>>(v, fc_w, fc_b,
                                                           x_lens, y);
}

// round 7
// speedup vs baseline: 1.4981x; 1.0092x over previous
#include <cuda_runtime.h>

#define BATCH 16
#define LEN   512
#define IDIM  300
#define HDIM  32
#define ODIM  15
#define GDIM  96
#define JH    256         // keys per attention block (half)
#define TI2   32          // i-rows per attention block
#define KSTR  36          // smem row stride (floats), 16B-aligned, conflict-free

typedef unsigned long long ull;

// Scratch as float4 arrays (guarantees 16B alignment for vector access)
__device__ float4 g_gx4 [BATCH * LEN * GDIM / 4];
__device__ float4 g_out4[BATCH * LEN * HDIM / 4];
__device__ float4 g_qh4 [BATCH * LEN * HDIM / 4];
__device__ float4 g_kh4 [BATCH * LEN * HDIM / 4];
#define g_gx  ((float*)g_gx4)
#define g_out ((float*)g_out4)
#define g_qh  ((float*)g_qh4)
#define g_kh  ((float*)g_kh4)

// attention partials
__device__ float g_ps  [BATCH * 2 * LEN];            // partial ssum
__device__ float g_pc  [BATCH * 2 * LEN * HDIM];     // partial ctx
__device__ float g_osum[BATCH * 2 * HDIM];           // partial out-sums

__device__ __forceinline__ float tanh_fast(float x) {
    float y;
    asm("tanh.approx.f32 %0, %1;" : "=f"(y) : "f"(x));
    return y;
}
__device__ __forceinline__ ull ffma2u(ull a, ull b, ull c) {
    ull d;
    asm("fma.rn.f32x2 %0, %1, %2, %3;" : "=l"(d) : "l"(a), "l"(b), "l"(c));
    return d;
}
__device__ __forceinline__ ull add2u(ull a, ull b) {
    ull d;
    asm("add.rn.f32x2 %0, %1, %2;" : "=l"(d) : "l"(a), "l"(b));
    return d;
}
__device__ __forceinline__ ull pack2(float lo, float hi) {
    ull d;
    asm("mov.b64 %0, {%1, %2};" : "=l"(d) : "f"(lo), "f"(hi));
    return d;
}
__device__ __forceinline__ float hsum2(ull a) {
    float lo, hi;
    asm("mov.b64 {%0, %1}, %2;" : "=f"(lo), "=f"(hi) : "l"(a));
    return lo + hi;
}

// ---------------------------------------------------------------------------
// K1: gx = x @ w_ih^T + b_ih   (M=8192, N=96, K=300)
// ---------------------------------------------------------------------------
__global__ __launch_bounds__(256) void gx_kernel(
    const float* __restrict__ x,
    const float* __restrict__ w_ih,
    const float* __restrict__ b_ih)
{
    __shared__ float xs[16][65];
    __shared__ float ws[16][97];

    const int m0 = blockIdx.x * 64;
    const int tx = threadIdx.x & 15;
    const int ty = threadIdx.x >> 4;

    float acc[4][6];
#pragma unroll
    for (int i = 0; i < 4; i++)
#pragma unroll
        for (int j = 0; j < 6; j++) acc[i][j] = 0.f;

    for (int kt = 0; kt < IDIM; kt += 16) {
        for (int idx = threadIdx.x; idx < 64 * 16; idx += 256) {
            int r = idx >> 4, kk = idx & 15;
            int k = kt + kk;
            xs[kk][r] = (k < IDIM) ? x[(m0 + r) * IDIM + k] : 0.f;
        }
        for (int idx = threadIdx.x; idx < 96 * 16; idx += 256) {
            int c = idx >> 4, kk = idx & 15;
            int k = kt + kk;
            ws[kk][c] = (k < IDIM) ? w_ih[c * IDIM + k] : 0.f;
        }
        __syncthreads();
#pragma unroll
        for (int kk = 0; kk < 16; kk++) {
            float xv[4], wv[6];
#pragma unroll
            for (int i = 0; i < 4; i++) xv[i] = xs[kk][ty * 4 + i];
#pragma unroll
            for (int j = 0; j < 6; j++) wv[j] = ws[kk][tx * 6 + j];
#pragma unroll
            for (int i = 0; i < 4; i++)
#pragma unroll
                for (int j = 0; j < 6; j++)
                    acc[i][j] = fmaf(xv[i], wv[j], acc[i][j]);
        }
        __syncthreads();
    }
#pragma unroll
    for (int i = 0; i < 4; i++) {
        int m = m0 + ty * 4 + i;
#pragma unroll
        for (int j = 0; j < 6; j++) {
            int c = tx * 6 + j;
            g_gx[m * GDIM + c] = acc[i][j] + b_ih[c];
        }
    }
}

// ---------------------------------------------------------------------------
// K2: GRU recurrence. One warp per batch. Packed-pair shfl broadcast,
// FFMA2 split chains, depth-4 gx prefetch. No smem, no barriers.
// ---------------------------------------------------------------------------
__global__ __launch_bounds__(32) void gru_kernel(
    const float* __restrict__ w_hh,
    const float* __restrict__ b_hh,
    const float* __restrict__ h0,
    const int*   __restrict__ x_lens)
{
    const int b = blockIdx.x;
    const int h = threadIdx.x;

    const ull* w8 = (const ull*)w_hh;   // [96][16] packed pairs
    ull wr2[16], wz2[16], wn2[16];
#pragma unroll
    for (int k = 0; k < 16; k++) {
        wr2[k] = w8[(0 * HDIM + h) * 16 + k];
        wz2[k] = w8[(1 * HDIM + h) * 16 + k];
        wn2[k] = w8[(2 * HDIM + h) * 16 + k];
    }
    const ull brp = pack2(b_hh[h], 0.f);
    const ull bzp = pack2(b_hh[HDIM + h], 0.f);
    const ull bnp = pack2(b_hh[2 * HDIM + h], 0.f);

    float hcur = h0[b * HDIM + h];
    // maintain packed neighbor pair: lanes 2m,2m+1 both hold (h[2m],h[2m+1])
    float nb0 = __shfl_xor_sync(0xffffffffu, hcur, 1);
    ull hpair = (h & 1) ? pack2(nb0, hcur) : pack2(hcur, nb0);

    const int len = x_lens[b];
    const float* gxb = g_gx + (size_t)b * LEN * GDIM;
    float* outb = g_out + (size_t)b * LEN * HDIM;

    float rxb[4], zxb[4], nxb[4];
#pragma unroll
    for (int t = 0; t < 4; t++) {
        const float* p = gxb + t * GDIM;
        rxb[t] = p[h]; zxb[t] = p[HDIM + h]; nxb[t] = p[2 * HDIM + h];
    }

#pragma unroll 4
    for (int t = 0; t < LEN; t++) {
        const int s = t & 3;
        const float rx = rxb[s], zx = zxb[s], nx = nxb[s];
        if (t + 4 < LEN) {
            const float* p = gxb + (t + 4) * GDIM;
            rxb[s] = p[h]; zxb[s] = p[HDIM + h]; nxb[s] = p[2 * HDIM + h];
        }

        ull ra[4] = {brp, 0ull, 0ull, 0ull};
        ull za[4] = {bzp, 0ull, 0ull, 0ull};
        ull na[4] = {bnp, 0ull, 0ull, 0ull};
#pragma unroll
        for (int k = 0; k < 16; k++) {
            const ull h2 = __shfl_sync(0xffffffffu, hpair, 2 * k);
            const int p = k & 3;
            ra[p] = ffma2u(wr2[k], h2, ra[p]);
            za[p] = ffma2u(wz2[k], h2, za[p]);
            na[p] = ffma2u(wn2[k], h2, na[p]);
        }
        const float rh = hsum2(add2u(add2u(ra[0], ra[1]), add2u(ra[2], ra[3])));
        const float zh = hsum2(add2u(add2u(za[0], za[1]), add2u(za[2], za[3])));
        const float nh = hsum2(add2u(add2u(na[0], na[1]), add2u(na[2], na[3])));

        const float r = fmaf(tanh_fast((rx + rh) * 0.5f), 0.5f, 0.5f);
        const float z = fmaf(tanh_fast((zx + zh) * 0.5f), 0.5f, 0.5f);
        const float n = tanh_fast(fmaf(r, nh, nx));
        hcur = fmaf(z, hcur - n, n);

        const float nb = __shfl_xor_sync(0xffffffffu, hcur, 1);
        hpair = (h & 1) ? pack2(nb, hcur) : pack2(hcur, nb);

        outb[t * HDIM + h] = (t < len) ? hcur : 0.f;
    }
}

// ---------------------------------------------------------------------------
// K3: qh = out@fch_w^T, kh = out@fco_w^T
// ---------------------------------------------------------------------------
__global__ __launch_bounds__(256) void qk_kernel(
    const float* __restrict__ fch_w,
    const float* __restrict__ fco_w)
{
    __shared__ float wq[HDIM][HDIM + 1];
    __shared__ float wk[HDIM][HDIM + 1];
    __shared__ float os[8][HDIM];

    const int tid = threadIdx.x;
    for (int idx = tid; idx < HDIM * HDIM; idx += 256) {
        int c = idx >> 5, k = idx & 31;
        wq[k][c] = fch_w[c * HDIM + k];
        wk[k][c] = fco_w[c * HDIM + k];
    }
    const int m0 = blockIdx.x * 8;
    const int r = tid >> 5, c = tid & 31;
    os[r][c] = g_out[(m0 + r) * HDIM + c];
    __syncthreads();

    float aq = 0.f, ak = 0.f;
#pragma unroll
    for (int k = 0; k < HDIM; k++) {
        float o = os[r][k];
        aq = fmaf(o, wq[k][c], aq);
        ak = fmaf(o, wk[k][c], ak);
    }
    g_qh[(m0 + r) * HDIM + c] = aq;
    g_kh[(m0 + r) * HDIM + c] = ak;
}

// ---------------------------------------------------------------------------
// K4a: attention pass 1 over a half of the keys (256 rows -> 74KB smem,
// 3 blocks/SM). Emits partial (ssum, ctx[32]) per i; i_tile-0 blocks also
// emit partial osum.
// ---------------------------------------------------------------------------
__global__ __launch_bounds__(512) void attn1_kernel(
    const float* __restrict__ v,
    const int*   __restrict__ x_lens)
{
    extern __shared__ float sm[];
    float* ks  = sm;                   // [256][36]
    float* os  = ks + JH * KSTR;       // [256][36]
    float* vsh = os + JH * KSTR;       // 32
    float* red = vsh + 32;             // [16][33]

    const int b    = blockIdx.z;
    const int half = blockIdx.y;
    const int i0   = blockIdx.x * TI2;
    const int tid  = threadIdx.x;
    const int wid  = tid >> 5, lane = tid & 31;
    const int jbase = b * LEN + half * JH;

    for (int idx = tid; idx < JH * 8; idx += 512) {
        int j = idx >> 3, q = idx & 7;
        float4 kv = g_kh4[(jbase + j) * 8 + q];
        float4 ov = g_out4[(jbase + j) * 8 + q];
        *(float4*)(ks + j * KSTR + q * 4) = kv;
        *(float4*)(os + j * KSTR + q * 4) = ov;
    }
    if (tid < HDIM) vsh[tid] = v[tid];
    __syncthreads();

    // partial osum (only i_tile 0 blocks)
    if (blockIdx.x == 0) {
        float p = 0.f;
#pragma unroll
        for (int jj = 0; jj < JH / 16; jj++)
            p += os[(wid * (JH / 16) + jj) * KSTR + lane];
        red[wid * 33 + lane] = p;
        __syncthreads();
        if (tid < HDIM) {
            float t = 0.f;
#pragma unroll
            for (int w = 0; w < 16; w++) t += red[w * 33 + tid];
            g_osum[(b * 2 + half) * HDIM + tid] = t;
        }
    }

    const int len    = x_lens[b];                       // len >= 256 always
    const int kcount = (half == 0) ? JH : (len - JH);   // valid keys here
    const int chunks = (kcount + 31) >> 5;
    const int tail   = JH - chunks * 32;                // fully-padded rows

    float vr[HDIM];
#pragma unroll
    for (int h = 0; h < HDIM; h++) vr[h] = vsh[h];
    float S = 0.f;
#pragma unroll
    for (int h = 0; h < HDIM; h++) S += fabsf(vr[h]);

    for (int ii = wid; ii < TI2; ii += 16) {
        const int i = i0 + ii;
        const float* qrow = g_qh + (size_t)(b * LEN + i) * HDIM;

        union { float4 v4[8]; float f[HDIM]; } qu;
#pragma unroll
        for (int q = 0; q < 8; q++)
            qu.v4[q] = g_qh4[(b * LEN + i) * 8 + q];

        float ep = 0.f;
        if (tail > 0) {
            ep = vsh[lane] * tanh_fast(__ldg(qrow + lane));
#pragma unroll
            for (int s = 16; s > 0; s >>= 1)
                ep += __shfl_xor_sync(0xffffffffu, ep, s);
        }

        float ssum = 0.f, ctx = 0.f;
        for (int c = 0; c < chunks; c++) {
            const float* krow = ks + (c * 32 + lane) * KSTR;
            union { float4 v4[8]; float f[HDIM]; } ku;
#pragma unroll
            for (int q = 0; q < 8; q++)
                ku.v4[q] = *(const float4*)(krow + q * 4);

            float e = 0.f;
#pragma unroll
            for (int h = 0; h < HDIM; h++)
                e = fmaf(vr[h], tanh_fast(qu.f[h] + ku.f[h]), e);

            ssum += __expf(e - S);

            const float* orow = os + (c * 32) * KSTR + lane;
#pragma unroll
            for (int jj = 0; jj < 32; jj++) {
                float ej = __shfl_sync(0xffffffffu, e, jj);
                ctx = fmaf(ej, orow[jj * KSTR], ctx);
            }
        }
#pragma unroll
        for (int s = 16; s > 0; s >>= 1)
            ssum += __shfl_xor_sync(0xffffffffu, ssum, s);
        if (tail > 0) ssum += (float)tail * __expf(ep - S);

        const int base = (b * 2 + half) * LEN + i;
        g_pc[base * HDIM + lane] = ctx;
        if (lane == 0) g_ps[base] = ssum;
    }
}

// ---------------------------------------------------------------------------
// K4b: combiner: lse, ctx = c0+c1-lse*osum, fc head. One warp per i-row.
// ---------------------------------------------------------------------------
__global__ __launch_bounds__(256) void attn2_kernel(
    const float* __restrict__ v,
    const float* __restrict__ fc_w,
    const float* __restrict__ fc_b,
    float* __restrict__ y)
{
    __shared__ float fcw[ODIM][33];
    __shared__ float fcbs[16];
    __shared__ float cx[8][33];

    const int tid = threadIdx.x;
    const int wid = tid >> 5, lane = tid & 31;

    // FIX: strided load (480 elements > 256 threads)
    for (int idx = tid; idx < ODIM * HDIM; idx += 256) {
        int o = idx / HDIM, h = idx % HDIM;
        fcw[o][h] = fc_w[idx];
    }
    if (tid < ODIM) fcbs[tid] = fc_b[tid];

    float S = fabsf(v[lane]);
#pragma unroll
    for (int s = 16; s > 0; s >>= 1)
        S += __shfl_xor_sync(0xffffffffu, S, s);
    __syncthreads();

    const int r = blockIdx.x * 8 + wid;     // global row in [0, 8192)
    const int b = r >> 9, i = r & 511;
    const int base0 = (b * 2 + 0) * LEN + i;
    const int base1 = (b * 2 + 1) * LEN + i;

    const float ssum = g_ps[base0] + g_ps[base1];
    const float lse  = S + __logf(ssum);
    const float osv  = g_osum[(b * 2 + 0) * HDIM + lane] +
                       g_osum[(b * 2 + 1) * HDIM + lane];
    float ctx = g_pc[base0 * HDIM + lane] + g_pc[base1 * HDIM + lane]
              - lse * osv;

    cx[wid][lane] = ctx;
    __syncwarp();
    if (lane < ODIM) {
        float acc = fcbs[lane];
#pragma unroll
        for (int h = 0; h < HDIM; h++)
            acc = fmaf(fcw[lane][h], cx[wid][h], acc);
        y[(size_t)r * ODIM + lane] = acc;
    }
}

// ---------------------------------------------------------------------------
extern "C" void kernel_launch(void* const* d_in, const int* in_sizes, int n_in,
                              void* d_out, int out_size)
{
    const float* x      = (const float*)d_in[0];
    const int*   x_lens = (const int*)  d_in[1];
    const float* h0     = (const float*)d_in[2];
    const float* w_ih   = (const float*)d_in[3];
    const float* w_hh   = (const float*)d_in[4];
    const float* b_ih   = (const float*)d_in[5];
    const float* b_hh   = (const float*)d_in[6];
    const float* fc_w   = (const float*)d_in[7];
    const float* fc_b   = (const float*)d_in[8];
    const float* fch_w  = (const float*)d_in[9];
    const float* fco_w  = (const float*)d_in[10];
    const float* v      = (const float*)d_in[11];
    float* y = (float*)d_out;

    const size_t a1_smem = (size_t)(2 * JH * KSTR + 32 + 16 * 33 + 16)
                           * sizeof(float);
    cudaFuncSetAttribute(attn1_kernel,
                         cudaFuncAttributeMaxDynamicSharedMemorySize,
                         (int)a1_smem);

    gx_kernel <<<(BATCH * LEN) / 64, 256>>>(x, w_ih, b_ih);
    gru_kernel<<<BATCH, 32>>>(w_hh, b_hh, h0, x_lens);
    qk_kernel <<<(BATCH * LEN) / 8, 256>>>(fch_w, fco_w);
    attn1_kernel<<<dim3(LEN / TI2, 2, BATCH), 512, a1_smem>>>(v, x_lens);
    attn2_kernel<<<(BATCH * LEN) / 8, 256>>>(v, fc_w, fc_b, y);
}